// round 14
// baseline (speedup 1.0000x reference)
#include <cuda_runtime.h>

// out[t, 0, :] = inputs[t, :]
// out[t, l, :] = memory[l, :]  for l in [1, 64)
// T=2048, L=64, D=1024 (fp32). 512 MB pure-write kernel.
//
// R3 schedule (best measured: 76.8us = 6.67 TB/s) with halved block count:
// 512 threads/block, thread-halves cover rows l=lb and l=lb+32 of the same
// TT=16 t-chunk. Per-warp store streams are IDENTICAL to R3 (one contiguous
// 16x STG.128 streaming store run, register-held row), wave span unchanged
// (~74MB), warps/SM unchanged (64) — only block launch/drain count halves.
// Cross-hold timing variance is ~15% (same source measured 76.8 and 88.6us);
// judge on DRAM%% as well as dur.

constexpr int T  = 2048;
constexpr int L  = 64;
constexpr int D  = 1024;
constexpr int D4 = D / 4;            // 256 float4 per row
constexpr int ROW4 = L * D4;         // float4 per t
constexpr int TT = 16;               // t-values per block (4 MB chunk)
constexpr int CH = T / TT;           // 128 chunks along t
constexpr int LB = 32;               // blocks per chunk (each covers 2 rows)

__global__ __launch_bounds__(512, 4)
void sliding_window_memory_kernel(const float4* __restrict__ inp,
                                  const float4* __restrict__ mem,
                                  float4* __restrict__ out) {
    const int lb   = blockIdx.x;             // 0..31 (fast dim)
    const int t0   = blockIdx.y * TT;
    const int half = threadIdx.x >> 8;       // 0 or 1
    const int col  = threadIdx.x & 255;      // float4 column 0..255
    const int l    = lb + half * 32;         // row owned by this thread-half

    if (l == 0) {
        // slot 0 depends on t: copy inputs[t0..t0+TT), streaming reads
        const float4* ip = inp + (size_t)t0 * D4 + col;
        float4*       op = out + (size_t)t0 * ROW4 + col;
        #pragma unroll
        for (int i = 0; i < TT; ++i) {
            __stcs(op, __ldcs(ip));
            ip += D4;
            op += ROW4;
        }
    } else {
        // t-invariant row -> register-held, single contiguous store stream
        const float4 v = __ldg(mem + (size_t)l * D4 + col);
        float4* op = out + (size_t)t0 * ROW4 + (size_t)l * D4 + col;
        #pragma unroll
        for (int i = 0; i < TT; ++i) {
            __stcs(op, v);
            op += ROW4;
        }
    }
}

extern "C" void kernel_launch(void* const* d_in, const int* in_sizes, int n_in,
                              void* d_out, int out_size) {
    const float4* inp = (const float4*)d_in[0];   // [T, D] fp32
    const float4* mem = (const float4*)d_in[1];   // [L, D] fp32
    float4* out = (float4*)d_out;                 // [T, L, D] fp32

    dim3 grid(LB, CH);
    sliding_window_memory_kernel<<<grid, 512>>>(inp, mem, out);
}

// round 15
// speedup vs baseline: 1.0485x; 1.0485x over previous
#include <cuda_runtime.h>
#include <cstdint>

// out[t, 0, :] = inputs[t, :]
// out[t, l, :] = memory[l, :]  for l in [1, 64)
// T=2048, L=64, D=1024 (fp32). 512 MB pure-write kernel.
//
// TMA bulk-store variant: R3 schedule (grid x=l fast, y=t-chunk, TT=16) but
// l>=1 blocks stage their t-invariant 4KB row in SMEM once, then 16 threads
// each issue ONE cp.async.bulk (SMEM->GMEM, 4KB contiguous) to their t-slot.
// Rationale: STG-class kernels are pinned at ~71% DRAM on current holds; a
// 4KB bulk op presents a fully contiguous write granule to LTS/DRAM (better
// page/sector sequencing than interleaved 128B store wavefronts) and cuts
// store-issue ops 256x. l==0 blocks (inputs[t], 1.5% of grid) keep STG path.

constexpr int T  = 2048;
constexpr int L  = 64;
constexpr int D  = 1024;
constexpr int D4 = D / 4;            // 256 float4 per row (4KB)
constexpr int ROW4 = L * D4;         // float4 per t
constexpr int TT = 16;               // t-values per block (4 MB chunk)
constexpr int CH = T / TT;           // 128 chunks along t

__global__ __launch_bounds__(256, 8)
void sliding_window_memory_kernel(const float4* __restrict__ inp,
                                  const float4* __restrict__ mem,
                                  float4* __restrict__ out) {
    __shared__ alignas(128) float4 row[D4];   // 4KB staging

    const int l   = blockIdx.x;          // 0..63 (fast dim)
    const int t0  = blockIdx.y * TT;
    const int tid = threadIdx.x;         // 0..255

    if (l == 0) {
        // slot 0 depends on t: proven STG path (streaming loads + stores)
        const float4* ip = inp + (size_t)t0 * D4 + tid;
        float4*       op = out + (size_t)t0 * ROW4 + tid;
        #pragma unroll
        for (int i = 0; i < TT; ++i) {
            __stcs(op, __ldcs(ip));
            ip += D4;
            op += ROW4;
        }
    } else {
        // stage the t-invariant row once in SMEM
        row[tid] = __ldg(mem + (size_t)l * D4 + tid);
        __syncthreads();
        // order generic smem writes before async-proxy reads
        asm volatile("fence.proxy.async.shared::cta;" ::: "memory");

        if (tid < TT) {
            float4* dst = out + (size_t)(t0 + tid) * ROW4 + (size_t)l * D4;
            uint32_t src = (uint32_t)__cvta_generic_to_shared(row);
            asm volatile(
                "cp.async.bulk.global.shared::cta.bulk_group [%0], [%1], %2;"
                :: "l"(dst), "r"(src), "n"(D4 * 16) : "memory");
            asm volatile("cp.async.bulk.commit_group;" ::: "memory");
            asm volatile("cp.async.bulk.wait_group 0;" ::: "memory");
        }
    }
}

extern "C" void kernel_launch(void* const* d_in, const int* in_sizes, int n_in,
                              void* d_out, int out_size) {
    const float4* inp = (const float4*)d_in[0];   // [T, D] fp32
    const float4* mem = (const float4*)d_in[1];   // [L, D] fp32
    float4* out = (float4*)d_out;                 // [T, L, D] fp32

    dim3 grid(L, CH);
    sliding_window_memory_kernel<<<grid, 256>>>(inp, mem, out);
}

// round 16
// speedup vs baseline: 1.0545x; 1.0057x over previous
#include <cuda_runtime.h>
#include <cstdint>

// out[t, 0, :] = inputs[t, :]
// out[t, l, :] = memory[l, :]  for l in [1, 64)
// T=2048, L=64, D=1024 (fp32). 512 MB pure-write kernel.
//
// TMA bulk-store, 8KB granule. R14 (4KB granule) won on a matched hold
// (84.5us/74.5% DRAM vs 88.6/71% for STG). This round doubles the write
// granule while holding everything else fixed vs R14:
//   - block stages TWO adjacent l-rows (8KB, contiguous in dest)
//   - TT=8 t-values/block -> 8 threads issue one 8KB cp.async.bulk each
//   - grid = 32 pairs x 256 chunks = 8192 blocks (same as R14)
//   - wave span = ~37 chunks x 2MB = 74MB (same as R14)
// Only the granule changes: 16x4KB -> 8x8KB per block.
// lb==0 (rows 0,1; slot 0 is t-dependent) keeps the proven STG path.

constexpr int T  = 2048;
constexpr int L  = 64;
constexpr int D  = 1024;
constexpr int D4 = D / 4;            // 256 float4 per row (4KB)
constexpr int ROW4 = L * D4;         // float4 per t (256KB)
constexpr int TT = 8;                // t-values per block (2MB chunk)
constexpr int CH = T / TT;           // 256 chunks along t
constexpr int LP = 2;                // adjacent rows per block (8KB granule)
constexpr int LB = L / LP;           // 32 row-pairs per chunk

__global__ __launch_bounds__(256, 8)
void sliding_window_memory_kernel(const float4* __restrict__ inp,
                                  const float4* __restrict__ mem,
                                  float4* __restrict__ out) {
    __shared__ alignas(128) float4 rows[LP * D4];   // 8KB staging

    const int lb  = blockIdx.x;          // 0..31 (fast dim)
    const int l0  = lb * LP;             // first row of the pair
    const int t0  = blockIdx.y * TT;
    const int tid = threadIdx.x;         // 0..255

    if (lb == 0) {
        // rows 0 (inputs[t], t-dependent) and 1: STG path
        const float4 v1 = __ldg(mem + (size_t)D4 + tid);
        const float4* ip = inp + (size_t)t0 * D4 + tid;
        float4*       op = out + (size_t)t0 * ROW4 + tid;
        #pragma unroll
        for (int i = 0; i < TT; ++i) {
            __stcs(op,      __ldcs(ip));   // slot 0
            __stcs(op + D4, v1);           // slot 1
            ip += D4;
            op += ROW4;
        }
    } else {
        // stage two adjacent t-invariant rows (8KB contiguous in dest order)
        rows[tid]      = __ldg(mem + (size_t)l0 * D4 + tid);
        rows[tid + D4] = __ldg(mem + (size_t)l0 * D4 + tid + D4);
        __syncthreads();
        asm volatile("fence.proxy.async.shared::cta;" ::: "memory");

        if (tid < TT) {
            float4* dst = out + (size_t)(t0 + tid) * ROW4 + (size_t)l0 * D4;
            uint32_t src = (uint32_t)__cvta_generic_to_shared(rows);
            asm volatile(
                "cp.async.bulk.global.shared::cta.bulk_group [%0], [%1], %2;"
                :: "l"(dst), "r"(src), "n"(LP * D4 * 16) : "memory");
            asm volatile("cp.async.bulk.commit_group;" ::: "memory");
            asm volatile("cp.async.bulk.wait_group 0;" ::: "memory");
        }
    }
}

extern "C" void kernel_launch(void* const* d_in, const int* in_sizes, int n_in,
                              void* d_out, int out_size) {
    const float4* inp = (const float4*)d_in[0];   // [T, D] fp32
    const float4* mem = (const float4*)d_in[1];   // [L, D] fp32
    float4* out = (float4*)d_out;                 // [T, L, D] fp32

    dim3 grid(LB, CH);
    sliding_window_memory_kernel<<<grid, 256>>>(inp, mem, out);
}